// round 6
// baseline (speedup 1.0000x reference)
#include <cuda_runtime.h>
#include <cuda_bf16.h>
#include <math_constants.h>

#define BS 16
#define NQ 900
#define NC 91
#define NT 1600
#define NR (BS * NQ)
#define TQ 16           // queries per block in cost kernel
#define TT 320          // targets per block (160 threads x 2)

// Scratch (allocation-free rule: device global)
__device__ float g_prob[NR * NC];     // softmax probabilities [14400, 91]

// ---------------------------------------------------------------------------
// Packed f32x2 helpers (SASS FADD2/FMUL2/FFMA2 — PTX-only on Blackwell)
// ---------------------------------------------------------------------------
union F2 {
    unsigned long long u;
    float2 f;
};
__device__ __forceinline__ F2 mkf2(float lo, float hi) {
    F2 r; r.f.x = lo; r.f.y = hi; return r;
}
__device__ __forceinline__ F2 add2(F2 a, F2 b) {
    F2 r; asm("add.rn.f32x2 %0, %1, %2;" : "=l"(r.u) : "l"(a.u), "l"(b.u)); return r;
}
__device__ __forceinline__ F2 mul2(F2 a, F2 b) {
    F2 r; asm("mul.rn.f32x2 %0, %1, %2;" : "=l"(r.u) : "l"(a.u), "l"(b.u)); return r;
}
__device__ __forceinline__ F2 fma2(F2 a, F2 b, F2 c) {
    F2 r; asm("fma.rn.f32x2 %0, %1, %2, %3;" : "=l"(r.u) : "l"(a.u), "l"(b.u), "l"(c.u)); return r;
}
__device__ __forceinline__ float rcpa(float x) {
    float r; asm("rcp.approx.f32 %0, %1;" : "=f"(r) : "f"(x)); return r;
}

// ---------------------------------------------------------------------------
// Kernel 1: softmax over class dim, one warp per row. No max-subtraction
// (logits O(1), exp can't overflow; tol 1e-3).
// ---------------------------------------------------------------------------
__global__ void softmax_rows(const float* __restrict__ logits) {
    int row  = blockIdx.x * 8 + (threadIdx.x >> 5);
    int lane = threadIdx.x & 31;
    if (row >= NR) return;
    const float* in = logits + row * NC;

    float v0 = in[lane];
    float v1 = in[lane + 32];
    bool has2 = (lane + 64 < NC);
    float v2 = has2 ? in[lane + 64] : 0.0f;

    float e0 = __expf(v0);
    float e1 = __expf(v1);
    float e2 = has2 ? __expf(v2) : 0.0f;
    float s = e0 + e1 + e2;
    #pragma unroll
    for (int o = 16; o; o >>= 1) s += __shfl_xor_sync(0xffffffffu, s, o);

    float inv = rcpa(s);
    float* out = g_prob + row * NC;
    out[lane]      = e0 * inv;
    out[lane + 32] = e1 * inv;
    if (has2) out[lane + 64] = e2 * inv;
}

// ---------------------------------------------------------------------------
// Kernel 2: cost matrix, min/max-free, rescaled.
// Per axis: dh=qh-th, dl=ql-tl, D=|dh|+|dl|, fx=dh-dl (= qw-tw),
//   base = qw+tw = fx + 2tw;  2w = base-D (clamp 0);  2dx = base+D
// uni4 = 4qa+4ta - inter'  (inter'=4*inter, ac'=4*ac)
// C = 2.5(|ex|+|ey|) + 5(|fx|+|fy|) + 2 - p - 2*(inter'*ac' + uni4^2)*rcp(uni4*ac')
// ---------------------------------------------------------------------------
struct __align__(16) QEntry {
    float4 a;   // qlx,qlx,qhx,qhx
    float4 b;   // qly,qly,qhy,qhy
    float2 c;   // 4*qa, 4*qa
};
union Q4 { float4 v; F2 h[2]; };
union Q2 { float2 v; F2 h; };

__global__ void __launch_bounds__(160, 9) cost_kernel(
    const float* __restrict__ pred_boxes,
    const float* __restrict__ tgt_bbox,
    const int*   __restrict__ tgt_ids,
    float*       __restrict__ out)
{
    __shared__ QEntry sq[TQ];

    const int tid   = threadIdx.x;
    const int qbase = blockIdx.y * TQ;

    if (tid < TQ) {
        float4 b = reinterpret_cast<const float4*>(pred_boxes)[qbase + tid];
        float lx = b.x - 0.5f * b.z, hx = b.x + 0.5f * b.z;
        float ly = b.y - 0.5f * b.w, hy = b.y + 0.5f * b.w;
        float a4 = 4.0f * b.z * b.w;
        sq[tid].a = make_float4(lx, lx, hx, hx);
        sq[tid].b = make_float4(ly, ly, hy, hy);
        sq[tid].c = make_float2(a4, a4);
    }

    const int j0 = blockIdx.x * TT + 2 * tid;   // 5*320 = 1600 exact
    const int j1 = j0 + 1;

    float4 tc0 = reinterpret_cast<const float4*>(tgt_bbox)[j0];
    float4 tc1 = reinterpret_cast<const float4*>(tgt_bbox)[j1];
    // packed pre-negated target corners: -th, -tl per axis
    F2 nthx = mkf2(-fmaf(0.5f, tc0.z,  tc0.x), -fmaf(0.5f, tc1.z,  tc1.x));
    F2 ntlx = mkf2( fmaf(0.5f, tc0.z, -tc0.x),  fmaf(0.5f, tc1.z, -tc1.x));
    F2 nthy = mkf2(-fmaf(0.5f, tc0.w,  tc0.y), -fmaf(0.5f, tc1.w,  tc1.y));
    F2 ntly = mkf2( fmaf(0.5f, tc0.w, -tc0.y),  fmaf(0.5f, tc1.w, -tc1.y));
    F2 tw2x = mkf2(2.0f * tc0.z, 2.0f * tc1.z);
    F2 tw2y = mkf2(2.0f * tc0.w, 2.0f * tc1.w);
    F2 ta4  = mkf2(4.0f * tc0.z * tc0.w, 4.0f * tc1.z * tc1.w);

    const float* p0p = g_prob + (size_t)qbase * NC + tgt_ids[j0];
    const float* p1p = g_prob + (size_t)qbase * NC + tgt_ids[j1];
    float* op = out + (size_t)qbase * NT + j0;

    const F2 CM1 = mkf2(-1.0f, -1.0f);
    const F2 CM2 = mkf2(-2.0f, -2.0f);

    __syncthreads();

    #pragma unroll
    for (int qi = 0; qi < TQ; qi++) {
        Q4 A; A.v = sq[qi].a;            // LDS.128
        Q4 B; B.v = sq[qi].b;            // LDS.128
        Q2 Cq; Cq.v = sq[qi].c;          // LDS.64
        F2 qlx2 = A.h[0], qhx2 = A.h[1];
        F2 qly2 = B.h[0], qhy2 = B.h[1];
        F2 qa4  = Cq.h;

        float p0 = __ldg(p0p + qi * NC);
        float p1 = __ldg(p1p + qi * NC);

        // axis deltas
        F2 dhx = add2(qhx2, nthx);
        F2 dlx = add2(qlx2, ntlx);
        F2 dhy = add2(qhy2, nthy);
        F2 dly = add2(qly2, ntly);
        F2 fx  = fma2(dlx, CM1, dhx);    // dh - dl = qw - tw
        F2 fy  = fma2(dly, CM1, dhy);

        F2 Dx = mkf2(fabsf(dhx.f.x) + fabsf(dlx.f.x),
                     fabsf(dhx.f.y) + fabsf(dlx.f.y));
        F2 Dy = mkf2(fabsf(dhy.f.x) + fabsf(dly.f.x),
                     fabsf(dhy.f.y) + fabsf(dly.f.y));

        F2 bx = add2(fx, tw2x);          // qw + tw
        F2 by = add2(fy, tw2y);
        F2 ux = fma2(Dx, CM1, bx);       // 2*w (unclamped)
        F2 uy = fma2(Dy, CM1, by);
        F2 vx = add2(bx, Dx);            // 2*dx enclosing
        F2 vy = add2(by, Dy);

        F2 uxc = mkf2(fmaxf(ux.f.x, 0.0f), fmaxf(ux.f.y, 0.0f));
        F2 uyc = mkf2(fmaxf(uy.f.x, 0.0f), fmaxf(uy.f.y, 0.0f));

        F2 inter2 = mul2(uxc, uyc);          // 4*inter
        F2 sum4   = add2(qa4, ta4);          // 4*(qa+ta)
        F2 uni4   = fma2(inter2, CM1, sum4); // 4*uni
        F2 ac2    = mul2(vx, vy);            // 4*ac
        F2 prod2  = mul2(uni4, ac2);         // 16*uni*ac
        F2 r2     = mkf2(rcpa(prod2.f.x), rcpa(prod2.f.y));
        F2 iac2   = mul2(inter2, ac2);
        F2 S2     = fma2(uni4, uni4, iac2);  // 16*(inter*ac + uni^2)
        F2 mr2    = mul2(r2, CM2);           // -2/(16*uni*ac)

        // L1 cost pieces
        F2 ex = add2(dhx, dlx);              // 2*(qc - tc)
        F2 ey = add2(dhy, dly);
        float t0 = fmaf(fabsf(ex.f.x) + fabsf(ey.f.x), 2.5f,
                   fmaf(fabsf(fx.f.x) + fabsf(fy.f.x), 5.0f, 2.0f - p0));
        float t1 = fmaf(fabsf(ex.f.y) + fabsf(ey.f.y), 2.5f,
                   fmaf(fabsf(fx.f.y) + fabsf(fy.f.y), 5.0f, 2.0f - p1));

        F2 C2 = fma2(S2, mr2, mkf2(t0, t1));

        *reinterpret_cast<float2*>(op + qi * NT) = C2.f;
    }
}

// ---------------------------------------------------------------------------
extern "C" void kernel_launch(void* const* d_in, const int* in_sizes, int n_in,
                              void* d_out, int out_size)
{
    const float* pred_logits = (const float*)d_in[0];
    const float* pred_boxes  = (const float*)d_in[1];
    const float* tgt_bbox    = (const float*)d_in[2];
    const int*   tgt_ids     = (const int*)d_in[3];
    float* out = (float*)d_out;

    softmax_rows<<<(NR + 7) / 8, 256>>>(pred_logits);
    dim3 grid(NT / TT, NR / TQ);
    cost_kernel<<<grid, 160>>>(pred_boxes, tgt_bbox, tgt_ids, out);
}

// round 7
// speedup vs baseline: 1.0785x; 1.0785x over previous
#include <cuda_runtime.h>
#include <cuda_bf16.h>
#include <math_constants.h>

#define BS 16
#define NQ 900
#define NC 91
#define NT 1600
#define NR (BS * NQ)
#define TQ 8            // queries per block in cost kernel
#define TT 320          // targets per block (160 threads x 2)

// Scratch (allocation-free rule: device global)
__device__ float g_prob[NR * NC];     // softmax probabilities [14400, 91]

// ---------------------------------------------------------------------------
// Packed f32x2 helpers (SASS FADD2/FMUL2/FFMA2 — PTX-only on Blackwell)
// ---------------------------------------------------------------------------
union F2 {
    unsigned long long u;
    float2 f;
};
__device__ __forceinline__ F2 mkf2(float lo, float hi) {
    F2 r; r.f.x = lo; r.f.y = hi; return r;
}
__device__ __forceinline__ F2 add2(F2 a, F2 b) {
    F2 r; asm("add.rn.f32x2 %0, %1, %2;" : "=l"(r.u) : "l"(a.u), "l"(b.u)); return r;
}
__device__ __forceinline__ F2 mul2(F2 a, F2 b) {
    F2 r; asm("mul.rn.f32x2 %0, %1, %2;" : "=l"(r.u) : "l"(a.u), "l"(b.u)); return r;
}
__device__ __forceinline__ F2 fma2(F2 a, F2 b, F2 c) {
    F2 r; asm("fma.rn.f32x2 %0, %1, %2, %3;" : "=l"(r.u) : "l"(a.u), "l"(b.u), "l"(c.u)); return r;
}
__device__ __forceinline__ float rcpa(float x) {
    float r; asm("rcp.approx.f32 %0, %1;" : "=f"(r) : "f"(x)); return r;
}

// ---------------------------------------------------------------------------
// Kernel 1: softmax over class dim, one warp per row. No max-subtraction
// (logits O(1), exp can't overflow; tol 1e-3).
// ---------------------------------------------------------------------------
__global__ void softmax_rows(const float* __restrict__ logits) {
    int row  = blockIdx.x * 8 + (threadIdx.x >> 5);
    int lane = threadIdx.x & 31;
    if (row >= NR) return;
    const float* in = logits + row * NC;

    float v0 = in[lane];
    float v1 = in[lane + 32];
    bool has2 = (lane + 64 < NC);
    float v2 = has2 ? in[lane + 64] : 0.0f;

    float e0 = __expf(v0);
    float e1 = __expf(v1);
    float e2 = has2 ? __expf(v2) : 0.0f;
    float s = e0 + e1 + e2;
    #pragma unroll
    for (int o = 16; o; o >>= 1) s += __shfl_xor_sync(0xffffffffu, s, o);

    float inv = rcpa(s);
    float* out = g_prob + row * NC;
    out[lane]      = e0 * inv;
    out[lane + 32] = e1 * inv;
    if (has2) out[lane + 64] = e2 * inv;
}

// ---------------------------------------------------------------------------
// Kernel 2: cost matrix, min/max-free, prob rows staged in smem.
// Per axis: dh=qh-th, dl=ql-tl, D=|dh|+|dl|, fx=dh-dl,
//   base = qw+tw;  2w = base-D (clamp 0);  2dx = base+D
// uni4 = 4(qa+ta) - inter'   (inter'=4*inter, ac'=4*ac)
// C = 2.5(|ex|+|ey|) + 5(|fx|+|fy|) + 2 - p - 2*(inter'*ac' + uni4^2)*rcp(uni4*ac')
// ---------------------------------------------------------------------------
struct __align__(16) QEntry {
    float4 a;   // qlx,qlx,qhx,qhx
    float4 b;   // qly,qly,qhy,qhy
    float2 c;   // 4*qa, 4*qa
};
union Q4 { float4 v; F2 h[2]; };
union Q2 { float2 v; F2 h; };

__global__ void __launch_bounds__(160) cost_kernel(
    const float* __restrict__ pred_boxes,
    const float* __restrict__ tgt_bbox,
    const int*   __restrict__ tgt_ids,
    float*       __restrict__ out)
{
    __shared__ QEntry sq[TQ];
    __shared__ float  sprob[TQ * NC];   // prob rows qbase..qbase+TQ-1

    const int tid   = threadIdx.x;
    const int qbase = blockIdx.y * TQ;

    if (tid < TQ) {
        float4 b = reinterpret_cast<const float4*>(pred_boxes)[qbase + tid];
        float lx = b.x - 0.5f * b.z, hx = b.x + 0.5f * b.z;
        float ly = b.y - 0.5f * b.w, hy = b.y + 0.5f * b.w;
        float a4 = 4.0f * b.z * b.w;
        sq[tid].a = make_float4(lx, lx, hx, hx);
        sq[tid].b = make_float4(ly, ly, hy, hy);
        sq[tid].c = make_float2(a4, a4);
    }

    // Stage TQ prob rows (contiguous in g_prob) into smem, coalesced.
    {
        const float* src = g_prob + (size_t)qbase * NC;
        #pragma unroll
        for (int k = 0; k < (TQ * NC + 159) / 160; k++) {
            int idx = tid + k * 160;
            if (idx < TQ * NC) sprob[idx] = src[idx];
        }
    }

    const int j0 = blockIdx.x * TT + 2 * tid;   // 5*320 = 1600 exact
    const int j1 = j0 + 1;

    float4 tc0 = reinterpret_cast<const float4*>(tgt_bbox)[j0];
    float4 tc1 = reinterpret_cast<const float4*>(tgt_bbox)[j1];
    // packed pre-negated target corners: -th, -tl per axis
    F2 nthx = mkf2(-fmaf(0.5f, tc0.z,  tc0.x), -fmaf(0.5f, tc1.z,  tc1.x));
    F2 ntlx = mkf2( fmaf(0.5f, tc0.z, -tc0.x),  fmaf(0.5f, tc1.z, -tc1.x));
    F2 nthy = mkf2(-fmaf(0.5f, tc0.w,  tc0.y), -fmaf(0.5f, tc1.w,  tc1.y));
    F2 ntly = mkf2( fmaf(0.5f, tc0.w, -tc0.y),  fmaf(0.5f, tc1.w, -tc1.y));
    F2 tw2x = mkf2(2.0f * tc0.z, 2.0f * tc1.z);
    F2 tw2y = mkf2(2.0f * tc0.w, 2.0f * tc1.w);
    F2 ta4  = mkf2(4.0f * tc0.z * tc0.w, 4.0f * tc1.z * tc1.w);

    const int id0 = tgt_ids[j0];
    const int id1 = tgt_ids[j1];
    float* op = out + (size_t)qbase * NT + j0;

    const F2 CM1 = mkf2(-1.0f, -1.0f);
    const F2 CM2 = mkf2(-2.0f, -2.0f);

    __syncthreads();

    #pragma unroll
    for (int qi = 0; qi < TQ; qi++) {
        Q4 A; A.v = sq[qi].a;            // LDS.128 broadcast
        Q4 B; B.v = sq[qi].b;            // LDS.128 broadcast
        Q2 Cq; Cq.v = sq[qi].c;          // LDS.64  broadcast
        F2 qlx2 = A.h[0], qhx2 = A.h[1];
        F2 qly2 = B.h[0], qhy2 = B.h[1];
        F2 qa4  = Cq.h;

        // prob gather from smem (29-cyc LDS instead of ~234-cyc L2 LDG)
        float p0 = sprob[qi * NC + id0];
        float p1 = sprob[qi * NC + id1];

        // axis deltas
        F2 dhx = add2(qhx2, nthx);
        F2 dlx = add2(qlx2, ntlx);
        F2 dhy = add2(qhy2, nthy);
        F2 dly = add2(qly2, ntly);
        F2 fx  = fma2(dlx, CM1, dhx);    // dh - dl = qw - tw
        F2 fy  = fma2(dly, CM1, dhy);

        F2 Dx = mkf2(fabsf(dhx.f.x) + fabsf(dlx.f.x),
                     fabsf(dhx.f.y) + fabsf(dlx.f.y));
        F2 Dy = mkf2(fabsf(dhy.f.x) + fabsf(dly.f.x),
                     fabsf(dhy.f.y) + fabsf(dly.f.y));

        F2 bx = add2(fx, tw2x);          // qw + tw
        F2 by = add2(fy, tw2y);
        F2 ux = fma2(Dx, CM1, bx);       // 2*w (unclamped)
        F2 uy = fma2(Dy, CM1, by);
        F2 vx = add2(bx, Dx);            // 2*dx enclosing
        F2 vy = add2(by, Dy);

        F2 uxc = mkf2(fmaxf(ux.f.x, 0.0f), fmaxf(ux.f.y, 0.0f));
        F2 uyc = mkf2(fmaxf(uy.f.x, 0.0f), fmaxf(uy.f.y, 0.0f));

        F2 inter2 = mul2(uxc, uyc);          // 4*inter
        F2 sum4   = add2(qa4, ta4);          // 4*(qa+ta)
        F2 uni4   = fma2(inter2, CM1, sum4); // 4*uni
        F2 ac2    = mul2(vx, vy);            // 4*ac
        F2 prod2  = mul2(uni4, ac2);         // 16*uni*ac
        F2 r2     = mkf2(rcpa(prod2.f.x), rcpa(prod2.f.y));
        F2 iac2   = mul2(inter2, ac2);
        F2 S2     = fma2(uni4, uni4, iac2);  // 16*(inter*ac + uni^2)
        F2 mr2    = mul2(r2, CM2);           // -2/(16*uni*ac)

        // L1 cost pieces
        F2 ex = add2(dhx, dlx);              // 2*(qc - tc)
        F2 ey = add2(dhy, dly);
        float t0 = fmaf(fabsf(ex.f.x) + fabsf(ey.f.x), 2.5f,
                   fmaf(fabsf(fx.f.x) + fabsf(fy.f.x), 5.0f, 2.0f - p0));
        float t1 = fmaf(fabsf(ex.f.y) + fabsf(ey.f.y), 2.5f,
                   fmaf(fabsf(fx.f.y) + fabsf(fy.f.y), 5.0f, 2.0f - p1));

        F2 C2 = fma2(S2, mr2, mkf2(t0, t1));

        *reinterpret_cast<float2*>(op + qi * NT) = C2.f;
    }
}

// ---------------------------------------------------------------------------
extern "C" void kernel_launch(void* const* d_in, const int* in_sizes, int n_in,
                              void* d_out, int out_size)
{
    const float* pred_logits = (const float*)d_in[0];
    const float* pred_boxes  = (const float*)d_in[1];
    const float* tgt_bbox    = (const float*)d_in[2];
    const int*   tgt_ids     = (const int*)d_in[3];
    float* out = (float*)d_out;

    softmax_rows<<<(NR + 7) / 8, 256>>>(pred_logits);
    dim3 grid(NT / TT, NR / TQ);
    cost_kernel<<<grid, 160>>>(pred_boxes, tgt_bbox, tgt_ids, out);
}

// round 8
// speedup vs baseline: 1.1286x; 1.0465x over previous
#include <cuda_runtime.h>
#include <cuda_bf16.h>
#include <math_constants.h>

#define BS 16
#define NQ 900
#define NC 91
#define NT 1600
#define NR (BS * NQ)
#define TQ 8            // queries per block in cost kernel
#define TT 320          // targets per block (160 threads x 2)

// Scratch (allocation-free rule: device global)
// NOTE: holds (2 - prob), the exact term the cost formula needs.
__device__ float g_prob[NR * NC];

// ---------------------------------------------------------------------------
// Packed f32x2 helpers (SASS FADD2/FMUL2/FFMA2 — PTX-only on Blackwell)
// ---------------------------------------------------------------------------
union F2 {
    unsigned long long u;
    float2 f;
};
__device__ __forceinline__ F2 mkf2(float lo, float hi) {
    F2 r; r.f.x = lo; r.f.y = hi; return r;
}
__device__ __forceinline__ F2 add2(F2 a, F2 b) {
    F2 r; asm("add.rn.f32x2 %0, %1, %2;" : "=l"(r.u) : "l"(a.u), "l"(b.u)); return r;
}
__device__ __forceinline__ F2 mul2(F2 a, F2 b) {
    F2 r; asm("mul.rn.f32x2 %0, %1, %2;" : "=l"(r.u) : "l"(a.u), "l"(b.u)); return r;
}
__device__ __forceinline__ F2 fma2(F2 a, F2 b, F2 c) {
    F2 r; asm("fma.rn.f32x2 %0, %1, %2, %3;" : "=l"(r.u) : "l"(a.u), "l"(b.u), "l"(c.u)); return r;
}
__device__ __forceinline__ float rcpa(float x) {
    float r; asm("rcp.approx.f32 %0, %1;" : "=f"(r) : "f"(x)); return r;
}

// ---------------------------------------------------------------------------
// Kernel 1: softmax over class dim, one warp per row. Stores (2 - softmax).
// No max-subtraction (logits O(1), exp can't overflow; tol 1e-3).
// ---------------------------------------------------------------------------
__global__ void softmax_rows(const float* __restrict__ logits) {
    int row  = blockIdx.x * 8 + (threadIdx.x >> 5);
    int lane = threadIdx.x & 31;
    if (row >= NR) return;
    const float* in = logits + row * NC;

    float v0 = in[lane];
    float v1 = in[lane + 32];
    bool has2 = (lane + 64 < NC);
    float v2 = has2 ? in[lane + 64] : 0.0f;

    float e0 = __expf(v0);
    float e1 = __expf(v1);
    float e2 = has2 ? __expf(v2) : 0.0f;
    float s = e0 + e1 + e2;
    #pragma unroll
    for (int o = 16; o; o >>= 1) s += __shfl_xor_sync(0xffffffffu, s, o);

    float inv = rcpa(s);
    float* out = g_prob + row * NC;
    out[lane]      = fmaf(-e0, inv, 2.0f);
    out[lane + 32] = fmaf(-e1, inv, 2.0f);
    if (has2) out[lane + 64] = fmaf(-e2, inv, 2.0f);
}

// ---------------------------------------------------------------------------
// Kernel 2: cost matrix, min/max-free, prob gathers front-batched.
// Per axis: dh=qh-th, dl=ql-tl, D=|dh|+|dl|, fx=dh-dl,
//   base = qw+tw;  2w = base-D (clamp 0);  2dx = base+D
// uni4 = 4(qa+ta) - inter'   (inter'=4*inter, ac'=4*ac)
// C = 2.5(|ex|+|ey|) + 5(|fx|+|fy|) + (2-p) - 2*(inter'*ac' + uni4^2)*rcp(uni4*ac')
// ---------------------------------------------------------------------------
struct __align__(16) QEntry {
    float4 a;   // qlx,qlx,qhx,qhx
    float4 b;   // qly,qly,qhy,qhy
    float2 c;   // 4*qa, 4*qa
};
union Q4 { float4 v; F2 h[2]; };
union Q2 { float2 v; F2 h; };

__global__ void __launch_bounds__(160) cost_kernel(
    const float* __restrict__ pred_boxes,
    const float* __restrict__ tgt_bbox,
    const int*   __restrict__ tgt_ids,
    float*       __restrict__ out)
{
    __shared__ QEntry sq[TQ];
    __shared__ float  sprob[TQ * NC];   // (2-prob) rows qbase..qbase+TQ-1

    const int tid   = threadIdx.x;
    const int qbase = blockIdx.y * TQ;

    if (tid < TQ) {
        float4 b = reinterpret_cast<const float4*>(pred_boxes)[qbase + tid];
        float lx = b.x - 0.5f * b.z, hx = b.x + 0.5f * b.z;
        float ly = b.y - 0.5f * b.w, hy = b.y + 0.5f * b.w;
        float a4 = 4.0f * b.z * b.w;
        sq[tid].a = make_float4(lx, lx, hx, hx);
        sq[tid].b = make_float4(ly, ly, hy, hy);
        sq[tid].c = make_float2(a4, a4);
    }

    // Stage TQ prob rows (contiguous in g_prob) into smem, coalesced.
    {
        const float* src = g_prob + (size_t)qbase * NC;
        #pragma unroll
        for (int k = 0; k < (TQ * NC + 159) / 160; k++) {
            int idx = tid + k * 160;
            if (idx < TQ * NC) sprob[idx] = src[idx];
        }
    }

    const int j0 = blockIdx.x * TT + 2 * tid;   // 5*320 = 1600 exact
    const int j1 = j0 + 1;

    float4 tc0 = reinterpret_cast<const float4*>(tgt_bbox)[j0];
    float4 tc1 = reinterpret_cast<const float4*>(tgt_bbox)[j1];
    // packed pre-negated target corners: -th, -tl per axis
    F2 nthx = mkf2(-fmaf(0.5f, tc0.z,  tc0.x), -fmaf(0.5f, tc1.z,  tc1.x));
    F2 ntlx = mkf2( fmaf(0.5f, tc0.z, -tc0.x),  fmaf(0.5f, tc1.z, -tc1.x));
    F2 nthy = mkf2(-fmaf(0.5f, tc0.w,  tc0.y), -fmaf(0.5f, tc1.w,  tc1.y));
    F2 ntly = mkf2( fmaf(0.5f, tc0.w, -tc0.y),  fmaf(0.5f, tc1.w, -tc1.y));
    F2 tw2x = mkf2(2.0f * tc0.z, 2.0f * tc1.z);
    F2 tw2y = mkf2(2.0f * tc0.w, 2.0f * tc1.w);
    F2 ta4  = mkf2(4.0f * tc0.z * tc0.w, 4.0f * tc1.z * tc1.w);

    const int id0 = tgt_ids[j0];
    const int id1 = tgt_ids[j1];
    float* op = out + (size_t)qbase * NT + j0;

    const F2 CM1 = mkf2(-1.0f, -1.0f);
    const F2 CM2 = mkf2(-2.0f, -2.0f);

    __syncthreads();

    // Front-batch all prob gathers: 16 independent LDS (MLP=16, one exposure)
    float pa[TQ], pb[TQ];
    #pragma unroll
    for (int qi = 0; qi < TQ; qi++) {
        pa[qi] = sprob[qi * NC + id0];
        pb[qi] = sprob[qi * NC + id1];
    }

    #pragma unroll
    for (int qi = 0; qi < TQ; qi++) {
        Q4 A; A.v = sq[qi].a;            // LDS.128 broadcast
        Q4 B; B.v = sq[qi].b;            // LDS.128 broadcast
        Q2 Cq; Cq.v = sq[qi].c;          // LDS.64  broadcast
        F2 qlx2 = A.h[0], qhx2 = A.h[1];
        F2 qly2 = B.h[0], qhy2 = B.h[1];
        F2 qa4  = Cq.h;

        // axis deltas
        F2 dhx = add2(qhx2, nthx);
        F2 dlx = add2(qlx2, ntlx);
        F2 dhy = add2(qhy2, nthy);
        F2 dly = add2(qly2, ntly);
        F2 fx  = fma2(dlx, CM1, dhx);    // dh - dl = qw - tw
        F2 fy  = fma2(dly, CM1, dhy);

        F2 Dx = mkf2(fabsf(dhx.f.x) + fabsf(dlx.f.x),
                     fabsf(dhx.f.y) + fabsf(dlx.f.y));
        F2 Dy = mkf2(fabsf(dhy.f.x) + fabsf(dly.f.x),
                     fabsf(dhy.f.y) + fabsf(dly.f.y));

        F2 bx = add2(fx, tw2x);          // qw + tw
        F2 by = add2(fy, tw2y);
        F2 ux = fma2(Dx, CM1, bx);       // 2*w (unclamped)
        F2 uy = fma2(Dy, CM1, by);
        F2 vx = add2(bx, Dx);            // 2*dx enclosing
        F2 vy = add2(by, Dy);

        F2 uxc = mkf2(fmaxf(ux.f.x, 0.0f), fmaxf(ux.f.y, 0.0f));
        F2 uyc = mkf2(fmaxf(uy.f.x, 0.0f), fmaxf(uy.f.y, 0.0f));

        F2 inter2 = mul2(uxc, uyc);          // 4*inter
        F2 sum4   = add2(qa4, ta4);          // 4*(qa+ta)
        F2 uni4   = fma2(inter2, CM1, sum4); // 4*uni
        F2 ac2    = mul2(vx, vy);            // 4*ac
        F2 prod2  = mul2(uni4, ac2);         // 16*uni*ac
        F2 r2     = mkf2(rcpa(prod2.f.x), rcpa(prod2.f.y));
        F2 iac2   = mul2(inter2, ac2);
        F2 S2     = fma2(uni4, uni4, iac2);  // 16*(inter*ac + uni^2)
        F2 mr2    = mul2(r2, CM2);           // -2/(16*uni*ac)

        // L1 cost pieces (pa/pb already hold 2-p)
        F2 ex = add2(dhx, dlx);              // 2*(qc - tc)
        F2 ey = add2(dhy, dly);
        float t0 = fmaf(fabsf(ex.f.x) + fabsf(ey.f.x), 2.5f,
                   fmaf(fabsf(fx.f.x) + fabsf(fy.f.x), 5.0f, pa[qi]));
        float t1 = fmaf(fabsf(ex.f.y) + fabsf(ey.f.y), 2.5f,
                   fmaf(fabsf(fx.f.y) + fabsf(fy.f.y), 5.0f, pb[qi]));

        F2 C2 = fma2(S2, mr2, mkf2(t0, t1));

        *reinterpret_cast<float2*>(op + qi * NT) = C2.f;
    }
}

// ---------------------------------------------------------------------------
extern "C" void kernel_launch(void* const* d_in, const int* in_sizes, int n_in,
                              void* d_out, int out_size)
{
    const float* pred_logits = (const float*)d_in[0];
    const float* pred_boxes  = (const float*)d_in[1];
    const float* tgt_bbox    = (const float*)d_in[2];
    const int*   tgt_ids     = (const int*)d_in[3];
    float* out = (float*)d_out;

    softmax_rows<<<(NR + 7) / 8, 256>>>(pred_logits);
    dim3 grid(NT / TT, NR / TQ);
    cost_kernel<<<grid, 160>>>(pred_boxes, tgt_bbox, tgt_ids, out);
}